// round 14
// baseline (speedup 1.0000x reference)
#include <cuda_runtime.h>
#include <cuda_bf16.h>
#include <math.h>
#include <stdint.h>

// Problem constants (dataset-fixed shapes)
#define B_SZ   1024
#define N_SZ   8192        // power of two -> fixed 13-step branchless search
#define M_C    3000        // N_COMMON
#define MP     3008        // padded M (multiple of 32, zero-filled tail)
#define EPS_B  1e-8f
#define NIT    12          // ceil(MP/256) points per thread
#define SPLITK 4
#define KB_TOT (MP / 32)   // 94 k-blocks total
#define KB_PER 24          // k-blocks per split (last split gets 22)

// ---------------- scratch (no runtime allocation allowed) ----------------
__device__ __align__(16) __nv_bfloat16 g_y1c[B_SZ * MP];
__device__ __align__(16) __nv_bfloat16 g_y2c[B_SZ * MP];
__device__ __align__(16) float g_part[SPLITK * B_SZ * B_SZ];   // split-K partials
__device__ float    g_sq1[B_SZ];
__device__ float    g_sq2[B_SZ];
__device__ unsigned g_min_enc;
__device__ unsigned g_max_enc;

// ordered-uint encoding of float (monotone for all finite values)
__device__ __forceinline__ unsigned f2ord(float f) {
    unsigned u = __float_as_uint(f);
    return (u & 0x80000000u) ? ~u : (u | 0x80000000u);
}
__device__ __forceinline__ float ord2f(unsigned k) {
    return __uint_as_float((k & 0x80000000u) ? (k & 0x7FFFFFFFu) : ~k);
}

// ---------------- kernel 0: reset encoded min/max (deterministic per call) --
__global__ void mm_init_kernel() {
    g_min_enc = 0xFFFFFFFFu;
    g_max_enc = 0u;
}

// ---------------- kernel 1: parallel batch-scalar min/max ----------------
__global__ void minmax_kernel(const float* __restrict__ x, int B, int N) {
    int tid = blockIdx.x * blockDim.x + threadIdx.x;
    int nthr = gridDim.x * blockDim.x;
    unsigned mn = 0xFFFFFFFFu, mx = 0u;
    for (int b = tid; b < B; b += nthr) {
        mn = min(mn, f2ord(__ldg(x + (size_t)b * N)));
        mx = max(mx, f2ord(__ldg(x + (size_t)b * N + (N - 1))));
    }
    #pragma unroll
    for (int o = 16; o > 0; o >>= 1) {
        mn = min(mn, __shfl_xor_sync(0xffffffffu, mn, o));
        mx = max(mx, __shfl_xor_sync(0xffffffffu, mx, o));
    }
    if ((threadIdx.x & 31) == 0) {
        atomicMin(&g_min_enc, mn);
        atomicMax(&g_max_enc, mx);
    }
}

// ---------------- kernel 2: interpolation, search/gather decoupled --------
// (R7 proven version) One block per row; x row in shared. 12 independent
// branchless 13-step lower_bound searches per thread, then batched gathers.
__global__ __launch_bounds__(256) void interp_kernel(
    const float* __restrict__ x,
    const float* __restrict__ y1,
    const float* __restrict__ y2,
    int N)
{
    __shared__ float sx[N_SZ];
    __shared__ float red1[8], red2[8];

    const int b   = blockIdx.x;
    const int tid = threadIdx.x;

    const float* xr  = x  + (size_t)b * N;
    const float* y1r = y1 + (size_t)b * N;
    const float* y2r = y2 + (size_t)b * N;
    __nv_bfloat16* o1 = g_y1c + (size_t)b * MP;
    __nv_bfloat16* o2 = g_y2c + (size_t)b * MP;

    const float4* xr4 = (const float4*)xr;
    for (int i = tid; i < N / 4; i += blockDim.x)
        ((float4*)sx)[i] = xr4[i];
    __syncthreads();

    const float xmin   = ord2f(g_min_enc);
    const float xmax   = ord2f(g_max_enc);
    const float range  = xmax - xmin;
    const float inv_m1 = 1.0f / (float)(M_C - 1);
    const float x0 = sx[0];
    const float xN = sx[N - 1];

    int   lo_a[NIT];
    float w_a[NIT];
    float msk[NIT];

    #pragma unroll
    for (int it = 0; it < NIT; it++) {
        const int m = tid + it * 256;
        int   lo = 0;
        float w  = 0.f, mk = 0.f;
        if (m < M_C) {
            float t  = (m == M_C - 1) ? 1.0f : (float)m * inv_m1;
            float xc = __fmaf_rn(t, range, xmin);
            #pragma unroll
            for (int s = N_SZ / 2; s > 0; s >>= 1)
                lo += (sx[lo + s - 1] < xc) ? s : 0;
            if (xc >= x0 && xc <= xN) {
                mk = 1.f;
                int li  = min(max(lo - 1, 0), N - 2);
                int hiI = min(lo, N - 1);
                float xl = sx[li], xh = sx[hiI];
                float denom = xh - xl;
                if (denom == 0.f) denom = 1.f;
                w = fminf(fmaxf((xc - xl) / (denom + 1e-9f), 0.f), 1.f);
            }
        }
        lo_a[it] = lo;
        w_a[it]  = w;
        msk[it]  = mk;
    }

    float a1v[NIT], b1v[NIT], a2v[NIT], b2v[NIT];
    #pragma unroll
    for (int it = 0; it < NIT; it++) {
        const int lo  = lo_a[it];
        const int li  = min(max(lo - 1, 0), N - 2);
        const int hiI = min(lo, N - 1);
        a1v[it] = __ldg(y1r + li);
        b1v[it] = __ldg(y1r + hiI);
        a2v[it] = __ldg(y2r + li);
        b2v[it] = __ldg(y2r + hiI);
    }

    float s1 = 0.f, s2 = 0.f;
    #pragma unroll
    for (int it = 0; it < NIT; it++) {
        const int m = tid + it * 256;
        if (m < MP) {
            const float w = w_a[it], mk = msk[it];
            float v1 = mk * __fmaf_rn(w, b1v[it] - a1v[it], a1v[it]);
            float v2 = mk * __fmaf_rn(w, b2v[it] - a2v[it], a2v[it]);
            o1[m] = __float2bfloat16(v1);
            o2[m] = __float2bfloat16(v2);
            s1 += v1 * v1;
            s2 += v2 * v2;
        }
    }

    #pragma unroll
    for (int o = 16; o > 0; o >>= 1) {
        s1 += __shfl_xor_sync(0xffffffffu, s1, o);
        s2 += __shfl_xor_sync(0xffffffffu, s2, o);
    }
    if ((tid & 31) == 0) { red1[tid >> 5] = s1; red2[tid >> 5] = s2; }
    __syncthreads();
    if (tid == 0) {
        float t1 = 0.f, t2 = 0.f;
        #pragma unroll
        for (int w = 0; w < 8; w++) { t1 += red1[w]; t2 += red2[w]; }
        g_sq1[b] = t1 * (1.0f / (float)M_C);
        g_sq2[b] = t2 * (1.0f / (float)M_C);
    }
}

// ---------------- kernel 3: split-K bf16 tensor-core GEMM -----------------
// 64x64 tiles, 128 threads (4 warps 2x2), warp tile 32x32: per k16 step
// 2 a-ldsm + 2 b-ldsm + 8 HMMA (MMA:LDSM = 2.0, halves L1 wavefronts/FLOP
// vs the 16x32 tile). SPLITK=4 -> grid 1024, launch_bounds(128,5) -> up to
// 5 CTAs/SM (20 warps). R11 double-buffered fragment pipeline, NSTAGE=4.
#define GBM 64
#define GBN 64
#define GBK 32
#define ROW_B 80                       // bytes per smem row (32 bf16 + pad)
#define SA_STAGE (GBM * ROW_B)         // 5120 B
#define SB_STAGE (GBN * ROW_B)         // 5120 B
#define NSTAGE 4
#define SB_BASE (NSTAGE * SA_STAGE)    // 20480
#define SMEM_TOT (SB_BASE + NSTAGE * SB_STAGE)  // 40960 B

__device__ __forceinline__ void cp16(uint32_t dst, const void* src) {
    asm volatile("cp.async.cg.shared.global [%0], [%1], 16;\n"
                 :: "r"(dst), "l"(src));
}
__device__ __forceinline__ void ldsm_x4(uint32_t addr, uint32_t& r0, uint32_t& r1,
                                        uint32_t& r2, uint32_t& r3) {
    asm volatile("ldmatrix.sync.aligned.m8n8.x4.shared.b16 {%0,%1,%2,%3}, [%4];\n"
                 : "=r"(r0), "=r"(r1), "=r"(r2), "=r"(r3) : "r"(addr));
}
__device__ __forceinline__ void mma16816(float* c, const uint32_t* a, const uint32_t* b) {
    asm volatile(
        "mma.sync.aligned.m16n8k16.row.col.f32.bf16.bf16.f32 "
        "{%0,%1,%2,%3}, {%4,%5,%6,%7}, {%8,%9}, {%0,%1,%2,%3};\n"
        : "+f"(c[0]), "+f"(c[1]), "+f"(c[2]), "+f"(c[3])
        : "r"(a[0]), "r"(a[1]), "r"(a[2]), "r"(a[3]), "r"(b[0]), "r"(b[1]));
}

__global__ __launch_bounds__(128, 5) void gemm_part_kernel(int B) {
    __shared__ __align__(16) unsigned char smem[SMEM_TOT];
    const uint32_t smem_u = (uint32_t)__cvta_generic_to_shared(smem);

    const int tid  = threadIdx.x;
    const int warp = tid >> 5;
    const int lane = tid & 31;
    const int kz   = blockIdx.z;
    const int kofs = kz * KB_PER;
    const int nkb  = min(KB_PER, KB_TOT - kofs);   // 24,24,24,22

    const __nv_bfloat16* Ag = g_y1c + (size_t)blockIdx.y * GBM * MP;
    const __nv_bfloat16* Bg = g_y2c + (size_t)blockIdx.x * GBN * MP;

    // loads: 512 16B-chunks over 128 threads = 2 A + 2 B per thread
    const int r  = tid >> 1;          // 0..63 row
    const int cb = (tid & 1) * 2;     // chunk pair base (0 or 2)

    auto load_stage = [&](int st, int kb) {
        const int k0 = (kofs + kb) * GBK;
        #pragma unroll
        for (int i = 0; i < 2; i++) {
            const int c16 = cb + i;
            cp16(smem_u + st * SA_STAGE + r * ROW_B + c16 * 16,
                 Ag + (size_t)r * MP + k0 + c16 * 8);
            cp16(smem_u + SB_BASE + st * SB_STAGE + r * ROW_B + c16 * 16,
                 Bg + (size_t)r * MP + k0 + c16 * 8);
        }
    };

    load_stage(0, 0); asm volatile("cp.async.commit_group;\n" ::);
    load_stage(1, 1); asm volatile("cp.async.commit_group;\n" ::);
    load_stage(2, 2); asm volatile("cp.async.commit_group;\n" ::);

    // 2x2 warp grid, warp tile 32x32
    const int wm = (warp >> 1) * 32;
    const int wn = (warp & 1) * 32;
    const int lr = lane & 7, q = lane >> 3;

    const uint32_t a_addr_base = smem_u + (wm + lr + (q & 1) * 8) * ROW_B + (q >> 1) * 16;
    const uint32_t b_addr_base = smem_u + SB_BASE + (wn + lr + (q >> 1) * 8) * ROW_B + (q & 1) * 16;

    // double-buffered fragments: 2 a-ldsm + 2 b-ldsm per k16 step
    uint32_t af[2][2][4], bf[2][2][4];
    auto ldsm_step = [&](int st, int s, int pb) {
        const uint32_t aS = a_addr_base + st * SA_STAGE + s * 32;
        const uint32_t bS = b_addr_base + st * SB_STAGE + s * 32;
        #pragma unroll
        for (int mf = 0; mf < 2; mf++)
            ldsm_x4(aS + (mf * 16) * ROW_B,
                    af[pb][mf][0], af[pb][mf][1], af[pb][mf][2], af[pb][mf][3]);
        #pragma unroll
        for (int p = 0; p < 2; p++)
            ldsm_x4(bS + (p * 16) * ROW_B,
                    bf[pb][p][0], bf[pb][p][1], bf[pb][p][2], bf[pb][p][3]);
    };

    float acc[2][4][4];
    #pragma unroll
    for (int mf = 0; mf < 2; mf++)
        #pragma unroll
        for (int nf = 0; nf < 4; nf++)
            #pragma unroll
            for (int rr = 0; rr < 4; rr++) acc[mf][nf][rr] = 0.f;

    auto mma_step = [&](int pb) {
        #pragma unroll
        for (int mf = 0; mf < 2; mf++)
            #pragma unroll
            for (int nf = 0; nf < 4; nf++) {
                uint32_t bb[2] = { bf[pb][nf >> 1][(nf & 1) * 2],
                                   bf[pb][nf >> 1][(nf & 1) * 2 + 1] };
                mma16816(acc[mf][nf], af[pb][mf], bb);
            }
    };

    asm volatile("cp.async.wait_group 2;\n" ::);
    __syncthreads();
    ldsm_step(0, 0, 0);
    int pb = 0;

    for (int kb = 0; kb < nkb; kb++) {
        const int st = kb % NSTAGE;
        asm volatile("cp.async.wait_group 1;\n" ::);
        __syncthreads();
        if (kb + 3 < nkb) load_stage((kb + 3) % NSTAGE, kb + 3);
        asm volatile("cp.async.commit_group;\n" ::);

        ldsm_step(st, 1, pb ^ 1);
        mma_step(pb);
        pb ^= 1;

        if (kb + 1 < nkb) ldsm_step((kb + 1) % NSTAGE, 0, pb ^ 1);
        mma_step(pb);
        pb ^= 1;
    }

    // store partials (coalesced float2)
    float* part = g_part + (size_t)kz * B_SZ * B_SZ;
    const int gm = blockIdx.y * GBM + wm;
    const int gn = blockIdx.x * GBN + wn;
    #pragma unroll
    for (int mf = 0; mf < 2; mf++) {
        #pragma unroll
        for (int h = 0; h < 2; h++) {
            const int i = gm + mf * 16 + (lane >> 2) + h * 8;
            #pragma unroll
            for (int nf = 0; nf < 4; nf++) {
                const int j = gn + nf * 8 + (lane & 3) * 2;
                float2 o = { acc[mf][nf][h * 2 + 0], acc[mf][nf][h * 2 + 1] };
                *(float2*)(part + (size_t)i * B + j) = o;
            }
        }
    }
}

// ---------------- kernel 4: combine partials + loss epilogue --------------
// One block per output row; 256 threads x float4 = 1024 cols.
__global__ __launch_bounds__(256) void loss_kernel(float* __restrict__ out, int B) {
    const int i  = blockIdx.x;
    const int j0 = threadIdx.x * 4;

    float4 p[SPLITK];
    #pragma unroll
    for (int k = 0; k < SPLITK; k++)
        p[k] = *(const float4*)(g_part + (size_t)k * B_SZ * B_SZ + (size_t)i * B + j0);

    const float s1    = g_sq1[i];
    const float base  = s1 + g_sq2[i] + EPS_B;   // reference quirk: both i-indexed
    const float scale = 2.0f / base;
    const float inv_m = 1.0f / (float)M_C;

    float4 o;
    #pragma unroll
    for (int e = 0; e < 4; e++) {
        float sum = 0.f;
        #pragma unroll
        for (int k = 0; k < SPLITK; k++) sum += ((const float*)&p[k])[e];
        float cross = sum * inv_m;
        float d = fmaxf(s1 + g_sq2[j0 + e] - 2.0f * cross, 0.f);
        ((float*)&o)[e] = sqrtf(d * scale);
    }
    *(float4*)(out + (size_t)i * B + j0) = o;
}

// ---------------- launch ----------------
extern "C" void kernel_launch(void* const* d_in, const int* in_sizes, int n_in,
                              void* d_out, int out_size) {
    const float* x  = (const float*)d_in[0];
    const float* y1 = (const float*)d_in[1];
    const float* y2 = (const float*)d_in[2];
    float* out = (float*)d_out;

    // out is [B, B] -> exact integer sqrt
    int B = 1;
    while ((long long)(B + 1) * (B + 1) <= (long long)out_size) B++;
    int N = in_sizes[0] / B;

    mm_init_kernel<<<1, 1>>>();
    minmax_kernel<<<16, 128>>>(x, B, N);
    interp_kernel<<<B, 256>>>(x, y1, y2, N);
    dim3 grid(B / GBN, B / GBM, SPLITK);   // (16, 16, 4) = 1024 CTAs
    gemm_part_kernel<<<grid, 128>>>(B);
    loss_kernel<<<B, 256>>>(out, B);
}

// round 15
// speedup vs baseline: 1.0008x; 1.0008x over previous
#include <cuda_runtime.h>
#include <cuda_bf16.h>
#include <math.h>
#include <stdint.h>

// Problem constants (dataset-fixed shapes)
#define B_SZ   1024
#define N_SZ   8192        // power of two -> fixed 13-step branchless search
#define M_C    3000        // N_COMMON
#define MP     3008        // padded M (multiple of 32, zero-filled tail)
#define EPS_B  1e-8f
#define CHUNK  4           // points per pass per thread
#define NPASS  3           // 4*3*256 = 3072 >= MP

// ---------------- scratch (no runtime allocation allowed) ----------------
__device__ __align__(16) __nv_bfloat16 g_y1c[B_SZ * MP];
__device__ __align__(16) __nv_bfloat16 g_y2c[B_SZ * MP];
__device__ float    g_sq1[B_SZ];
__device__ float    g_sq2[B_SZ];
__device__ unsigned g_min_enc;
__device__ unsigned g_max_enc;

// ordered-uint encoding of float (monotone for all finite values)
__device__ __forceinline__ unsigned f2ord(float f) {
    unsigned u = __float_as_uint(f);
    return (u & 0x80000000u) ? ~u : (u | 0x80000000u);
}
__device__ __forceinline__ float ord2f(unsigned k) {
    return __uint_as_float((k & 0x80000000u) ? (k & 0x7FFFFFFFu) : ~k);
}

// ---------------- kernel 0: reset encoded min/max (deterministic per call) --
__global__ void mm_init_kernel() {
    g_min_enc = 0xFFFFFFFFu;
    g_max_enc = 0u;
}

// ---------------- kernel 1: parallel batch-scalar min/max ----------------
__global__ void minmax_kernel(const float* __restrict__ x, int B, int N) {
    int tid = blockIdx.x * blockDim.x + threadIdx.x;
    int nthr = gridDim.x * blockDim.x;
    unsigned mn = 0xFFFFFFFFu, mx = 0u;
    for (int b = tid; b < B; b += nthr) {
        mn = min(mn, f2ord(__ldg(x + (size_t)b * N)));
        mx = max(mx, f2ord(__ldg(x + (size_t)b * N + (N - 1))));
    }
    #pragma unroll
    for (int o = 16; o > 0; o >>= 1) {
        mn = min(mn, __shfl_xor_sync(0xffffffffu, mn, o));
        mx = max(mx, __shfl_xor_sync(0xffffffffu, mx, o));
    }
    if ((threadIdx.x & 31) == 0) {
        atomicMin(&g_min_enc, mn);
        atomicMax(&g_max_enc, mx);
    }
}

// ---------------- kernel 2: interpolation, chunked search/gather ----------
// One block per row; x row in shared. Work split into 3 passes of 4 points
// per thread: search 4 (branchless 13-step, ILP), gather 4 (MLP 16), lerp +
// store 4. Cuts live registers ~2.5x vs the 12-wide version -> 4-5 blocks/SM
// instead of 2 -> fewer waves. Arithmetic and accumulation order identical.
__global__ __launch_bounds__(256) void interp_kernel(
    const float* __restrict__ x,
    const float* __restrict__ y1,
    const float* __restrict__ y2,
    int N)
{
    __shared__ float sx[N_SZ];
    __shared__ float red1[8], red2[8];

    const int b   = blockIdx.x;
    const int tid = threadIdx.x;

    const float* xr  = x  + (size_t)b * N;
    const float* y1r = y1 + (size_t)b * N;
    const float* y2r = y2 + (size_t)b * N;
    __nv_bfloat16* o1 = g_y1c + (size_t)b * MP;
    __nv_bfloat16* o2 = g_y2c + (size_t)b * MP;

    const float4* xr4 = (const float4*)xr;
    for (int i = tid; i < N / 4; i += blockDim.x)
        ((float4*)sx)[i] = xr4[i];
    __syncthreads();

    const float xmin   = ord2f(g_min_enc);
    const float xmax   = ord2f(g_max_enc);
    const float range  = xmax - xmin;
    const float inv_m1 = 1.0f / (float)(M_C - 1);
    const float x0 = sx[0];
    const float xN = sx[N - 1];

    float s1 = 0.f, s2 = 0.f;

    #pragma unroll 1
    for (int pass = 0; pass < NPASS; pass++) {
        int   lo_a[CHUNK];
        float w_a[CHUNK];
        float msk[CHUNK];

        // ---- search phase (4 independent branchless chains) ----
        #pragma unroll
        for (int c = 0; c < CHUNK; c++) {
            const int m = tid + (pass * CHUNK + c) * 256;
            int   lo = 0;
            float w  = 0.f, mk = 0.f;
            if (m < M_C) {
                float t  = (m == M_C - 1) ? 1.0f : (float)m * inv_m1;
                float xc = __fmaf_rn(t, range, xmin);
                #pragma unroll
                for (int s = N_SZ / 2; s > 0; s >>= 1)
                    lo += (sx[lo + s - 1] < xc) ? s : 0;
                if (xc >= x0 && xc <= xN) {
                    mk = 1.f;
                    int li  = min(max(lo - 1, 0), N - 2);
                    int hiI = min(lo, N - 1);
                    float xl = sx[li], xh = sx[hiI];
                    float denom = xh - xl;
                    if (denom == 0.f) denom = 1.f;
                    w = fminf(fmaxf((xc - xl) / (denom + 1e-9f), 0.f), 1.f);
                }
            }
            lo_a[c] = lo;
            w_a[c]  = w;
            msk[c]  = mk;
        }

        // ---- gather phase (all 16 loads issued before consumption) ----
        float a1v[CHUNK], b1v[CHUNK], a2v[CHUNK], b2v[CHUNK];
        #pragma unroll
        for (int c = 0; c < CHUNK; c++) {
            const int lo  = lo_a[c];
            const int li  = min(max(lo - 1, 0), N - 2);
            const int hiI = min(lo, N - 1);
            a1v[c] = __ldg(y1r + li);
            b1v[c] = __ldg(y1r + hiI);
            a2v[c] = __ldg(y2r + li);
            b2v[c] = __ldg(y2r + hiI);
        }

        // ---- lerp + store + accumulate ----
        #pragma unroll
        for (int c = 0; c < CHUNK; c++) {
            const int m = tid + (pass * CHUNK + c) * 256;
            if (m < MP) {
                const float w = w_a[c], mk = msk[c];
                float v1 = mk * __fmaf_rn(w, b1v[c] - a1v[c], a1v[c]);
                float v2 = mk * __fmaf_rn(w, b2v[c] - a2v[c], a2v[c]);
                o1[m] = __float2bfloat16(v1);
                o2[m] = __float2bfloat16(v2);
                s1 += v1 * v1;
                s2 += v2 * v2;
            }
        }
    }

    // per-row sq means
    #pragma unroll
    for (int o = 16; o > 0; o >>= 1) {
        s1 += __shfl_xor_sync(0xffffffffu, s1, o);
        s2 += __shfl_xor_sync(0xffffffffu, s2, o);
    }
    if ((tid & 31) == 0) { red1[tid >> 5] = s1; red2[tid >> 5] = s2; }
    __syncthreads();
    if (tid == 0) {
        float t1 = 0.f, t2 = 0.f;
        #pragma unroll
        for (int w = 0; w < 8; w++) { t1 += red1[w]; t2 += red2[w]; }
        g_sq1[b] = t1 * (1.0f / (float)M_C);
        g_sq2[b] = t2 * (1.0f / (float)M_C);
    }
}

// ---------------- kernel 3: bf16 tensor-core GEMM + fused loss epilogue ----
// (R11 measured-best net config) 64x64 tiles, 8 warps (4x2), grid 256,
// 2 CTAs/SM, 4-stage cp.async, register double-buffered fragments.
#define GBM 64
#define GBN 64
#define GBK 32
#define ROW_B 80                       // bytes per smem row (32 bf16 + pad)
#define SA_STAGE (GBM * ROW_B)         // 5120 B
#define SB_STAGE (GBN * ROW_B)         // 5120 B
#define NSTAGE 4
#define SB_BASE (NSTAGE * SA_STAGE)    // 20480
#define SMEM_TOT (SB_BASE + NSTAGE * SB_STAGE)  // 40960 B

__device__ __forceinline__ void cp16(uint32_t dst, const void* src) {
    asm volatile("cp.async.cg.shared.global [%0], [%1], 16;\n"
                 :: "r"(dst), "l"(src));
}
__device__ __forceinline__ void ldsm_x4(uint32_t addr, uint32_t& r0, uint32_t& r1,
                                        uint32_t& r2, uint32_t& r3) {
    asm volatile("ldmatrix.sync.aligned.m8n8.x4.shared.b16 {%0,%1,%2,%3}, [%4];\n"
                 : "=r"(r0), "=r"(r1), "=r"(r2), "=r"(r3) : "r"(addr));
}
__device__ __forceinline__ void mma16816(float* c, const uint32_t* a, const uint32_t* b) {
    asm volatile(
        "mma.sync.aligned.m16n8k16.row.col.f32.bf16.bf16.f32 "
        "{%0,%1,%2,%3}, {%4,%5,%6,%7}, {%8,%9}, {%0,%1,%2,%3};\n"
        : "+f"(c[0]), "+f"(c[1]), "+f"(c[2]), "+f"(c[3])
        : "r"(a[0]), "r"(a[1]), "r"(a[2]), "r"(a[3]), "r"(b[0]), "r"(b[1]));
}

__global__ __launch_bounds__(256, 2) void gemm_loss_kernel(float* __restrict__ out, int B) {
    __shared__ __align__(16) unsigned char smem[SMEM_TOT];
    const uint32_t smem_u = (uint32_t)__cvta_generic_to_shared(smem);

    const int tid  = threadIdx.x;
    const int warp = tid >> 5;
    const int lane = tid & 31;

    const __nv_bfloat16* Ag = g_y1c + (size_t)blockIdx.y * GBM * MP;
    const __nv_bfloat16* Bg = g_y2c + (size_t)blockIdx.x * GBN * MP;

    const int a_row0 = tid >> 2, a_c = tid & 3;   // 64 rows x 4 k-chunks

    const int nkb = MP / GBK;    // 94

    auto load_stage = [&](int st, int kb) {
        const int k0 = kb * GBK;
        cp16(smem_u + st * SA_STAGE + a_row0 * ROW_B + a_c * 16,
             Ag + (size_t)a_row0 * MP + k0 + a_c * 8);
        cp16(smem_u + SB_BASE + st * SB_STAGE + a_row0 * ROW_B + a_c * 16,
             Bg + (size_t)a_row0 * MP + k0 + a_c * 8);
    };

    load_stage(0, 0); asm volatile("cp.async.commit_group;\n" ::);
    load_stage(1, 1); asm volatile("cp.async.commit_group;\n" ::);
    load_stage(2, 2); asm volatile("cp.async.commit_group;\n" ::);

    const int wm = (warp >> 1) * 16;   // 4 warps along M
    const int wn = (warp & 1) * 32;    // 2 warps along N
    const int lr = lane & 7, q = lane >> 3;

    const uint32_t a_addr_base = smem_u + (wm + lr + (q & 1) * 8) * ROW_B + (q >> 1) * 16;
    const uint32_t b_addr_base = smem_u + SB_BASE + (wn + lr + (q >> 1) * 8) * ROW_B + (q & 1) * 16;

    // double-buffered fragments
    uint32_t af[2][4], bf[2][2][4];
    auto ldsm_step = [&](int st, int s, int pb) {
        const uint32_t aS = a_addr_base + st * SA_STAGE + s * 32;
        const uint32_t bS = b_addr_base + st * SB_STAGE + s * 32;
        ldsm_x4(aS, af[pb][0], af[pb][1], af[pb][2], af[pb][3]);
        ldsm_x4(bS,               bf[pb][0][0], bf[pb][0][1], bf[pb][0][2], bf[pb][0][3]);
        ldsm_x4(bS + 16 * ROW_B,  bf[pb][1][0], bf[pb][1][1], bf[pb][1][2], bf[pb][1][3]);
    };

    float acc[4][4];
    #pragma unroll
    for (int nf = 0; nf < 4; nf++)
        #pragma unroll
        for (int r = 0; r < 4; r++) acc[nf][r] = 0.f;

    auto mma_step = [&](int pb) {
        #pragma unroll
        for (int nf = 0; nf < 4; nf++) {
            uint32_t bb[2] = { bf[pb][nf >> 1][(nf & 1) * 2],
                               bf[pb][nf >> 1][(nf & 1) * 2 + 1] };
            mma16816(acc[nf], af[pb], bb);
        }
    };

    asm volatile("cp.async.wait_group 2;\n" ::);
    __syncthreads();
    ldsm_step(0, 0, 0);
    int pb = 0;

    for (int kb = 0; kb < nkb; kb++) {
        const int st = kb % NSTAGE;
        asm volatile("cp.async.wait_group 1;\n" ::);
        __syncthreads();
        if (kb + 3 < nkb) load_stage((kb + 3) % NSTAGE, kb + 3);
        asm volatile("cp.async.commit_group;\n" ::);

        ldsm_step(st, 1, pb ^ 1);
        mma_step(pb);
        pb ^= 1;

        if (kb + 1 < nkb) ldsm_step((kb + 1) % NSTAGE, 0, pb ^ 1);
        mma_step(pb);
        pb ^= 1;
    }

    // fused loss epilogue
    const float inv_m = 1.0f / (float)M_C;
    const int gm = blockIdx.y * GBM + wm;
    const int gn = blockIdx.x * GBN + wn;
    #pragma unroll
    for (int h = 0; h < 2; h++) {
        const int i = gm + (lane >> 2) + h * 8;
        const float s1 = g_sq1[i];
        const float base = s1 + g_sq2[i] + EPS_B;   // reference quirk: both i-indexed
        const float scale = 2.0f / base;
        #pragma unroll
        for (int nf = 0; nf < 4; nf++) {
            const int j = gn + nf * 8 + (lane & 3) * 2;
            float c0 = acc[nf][h * 2 + 0];
            float c1 = acc[nf][h * 2 + 1];
            float d0 = fmaxf(s1 + g_sq2[j]     - 2.0f * c0 * inv_m, 0.f);
            float d1 = fmaxf(s1 + g_sq2[j + 1] - 2.0f * c1 * inv_m, 0.f);
            float2 o = { sqrtf(d0 * scale), sqrtf(d1 * scale) };
            *(float2*)(out + (size_t)i * B + j) = o;
        }
    }
}

// ---------------- launch ----------------
extern "C" void kernel_launch(void* const* d_in, const int* in_sizes, int n_in,
                              void* d_out, int out_size) {
    const float* x  = (const float*)d_in[0];
    const float* y1 = (const float*)d_in[1];
    const float* y2 = (const float*)d_in[2];
    float* out = (float*)d_out;

    // out is [B, B] -> exact integer sqrt
    int B = 1;
    while ((long long)(B + 1) * (B + 1) <= (long long)out_size) B++;
    int N = in_sizes[0] / B;

    mm_init_kernel<<<1, 1>>>();
    minmax_kernel<<<16, 128>>>(x, B, N);
    interp_kernel<<<B, 256>>>(x, y1, y2, N);
    dim3 grid(B / GBN, B / GBM);   // (16, 16)
    gemm_loss_kernel<<<grid, 256>>>(out, B);
}

// round 16
// speedup vs baseline: 1.2910x; 1.2900x over previous
#include <cuda_runtime.h>
#include <cuda_bf16.h>
#include <math.h>
#include <stdint.h>

// Problem constants (dataset-fixed shapes)
#define B_SZ   1024
#define N_SZ   8192        // power of two -> fixed 13-step branchless search
#define M_C    3000        // N_COMMON
#define MP     3008        // padded M (multiple of 64, zero-filled tail)
#define EPS_B  1e-8f
#define NIT    12          // ceil(MP/256) points per thread

// ---------------- scratch (no runtime allocation allowed) ----------------
__device__ __align__(16) int8_t g_q1[B_SZ * MP];
__device__ __align__(16) int8_t g_q2[B_SZ * MP];
__device__ float    g_sq1[B_SZ];
__device__ float    g_sq2[B_SZ];
__device__ float    g_scl1[B_SZ];    // per-row dequant scale for y1c
__device__ float    g_scl2[B_SZ];    // per-row dequant scale for y2c
__device__ unsigned g_min_enc;
__device__ unsigned g_max_enc;

// ordered-uint encoding of float (monotone for all finite values)
__device__ __forceinline__ unsigned f2ord(float f) {
    unsigned u = __float_as_uint(f);
    return (u & 0x80000000u) ? ~u : (u | 0x80000000u);
}
__device__ __forceinline__ float ord2f(unsigned k) {
    return __uint_as_float((k & 0x80000000u) ? (k & 0x7FFFFFFFu) : ~k);
}

// ---------------- kernel 0: reset encoded min/max (deterministic per call) --
__global__ void mm_init_kernel() {
    g_min_enc = 0xFFFFFFFFu;
    g_max_enc = 0u;
}

// ---------------- kernel 1: parallel batch-scalar min/max ----------------
__global__ void minmax_kernel(const float* __restrict__ x, int B, int N) {
    int tid = blockIdx.x * blockDim.x + threadIdx.x;
    int nthr = gridDim.x * blockDim.x;
    unsigned mn = 0xFFFFFFFFu, mx = 0u;
    for (int b = tid; b < B; b += nthr) {
        mn = min(mn, f2ord(__ldg(x + (size_t)b * N)));
        mx = max(mx, f2ord(__ldg(x + (size_t)b * N + (N - 1))));
    }
    #pragma unroll
    for (int o = 16; o > 0; o >>= 1) {
        mn = min(mn, __shfl_xor_sync(0xffffffffu, mn, o));
        mx = max(mx, __shfl_xor_sync(0xffffffffu, mx, o));
    }
    if ((threadIdx.x & 31) == 0) {
        atomicMin(&g_min_enc, mn);
        atomicMax(&g_max_enc, mx);
    }
}

// ---------------- kernel 2: interpolation + per-row int8 quantization ----
// R7 search/gather structure (proven), then per-row maxabs reduce and
// symmetric int8 quantize: q = rint(v * 127/maxabs). sq sums stay fp32.
__global__ __launch_bounds__(256) void interp_kernel(
    const float* __restrict__ x,
    const float* __restrict__ y1,
    const float* __restrict__ y2,
    int N)
{
    __shared__ float sx[N_SZ];
    __shared__ float red1[8], red2[8], redm1[8], redm2[8];
    __shared__ float s_inv1, s_inv2;

    const int b   = blockIdx.x;
    const int tid = threadIdx.x;

    const float* xr  = x  + (size_t)b * N;
    const float* y1r = y1 + (size_t)b * N;
    const float* y2r = y2 + (size_t)b * N;
    int8_t* o1 = g_q1 + (size_t)b * MP;
    int8_t* o2 = g_q2 + (size_t)b * MP;

    const float4* xr4 = (const float4*)xr;
    for (int i = tid; i < N / 4; i += blockDim.x)
        ((float4*)sx)[i] = xr4[i];
    __syncthreads();

    const float xmin   = ord2f(g_min_enc);
    const float xmax   = ord2f(g_max_enc);
    const float range  = xmax - xmin;
    const float inv_m1 = 1.0f / (float)(M_C - 1);
    const float x0 = sx[0];
    const float xN = sx[N - 1];

    int   lo_a[NIT];
    float w_a[NIT];
    float msk[NIT];

    // ---- phase A: independent branchless searches ----
    #pragma unroll
    for (int it = 0; it < NIT; it++) {
        const int m = tid + it * 256;
        int   lo = 0;
        float w  = 0.f, mk = 0.f;
        if (m < M_C) {
            float t  = (m == M_C - 1) ? 1.0f : (float)m * inv_m1;
            float xc = __fmaf_rn(t, range, xmin);
            #pragma unroll
            for (int s = N_SZ / 2; s > 0; s >>= 1)
                lo += (sx[lo + s - 1] < xc) ? s : 0;
            if (xc >= x0 && xc <= xN) {
                mk = 1.f;
                int li  = min(max(lo - 1, 0), N - 2);
                int hiI = min(lo, N - 1);
                float xl = sx[li], xh = sx[hiI];
                float denom = xh - xl;
                if (denom == 0.f) denom = 1.f;
                w = fminf(fmaxf((xc - xl) / (denom + 1e-9f), 0.f), 1.f);
            }
        }
        lo_a[it] = lo;
        w_a[it]  = w;
        msk[it]  = mk;
    }

    // ---- phase B: batched gathers ----
    float a1v[NIT], b1v[NIT], a2v[NIT], b2v[NIT];
    #pragma unroll
    for (int it = 0; it < NIT; it++) {
        const int lo  = lo_a[it];
        const int li  = min(max(lo - 1, 0), N - 2);
        const int hiI = min(lo, N - 1);
        a1v[it] = __ldg(y1r + li);
        b1v[it] = __ldg(y1r + hiI);
        a2v[it] = __ldg(y2r + li);
        b2v[it] = __ldg(y2r + hiI);
    }

    // ---- phase C: lerp (values kept in regs), accumulate sums + maxabs ----
    float v1a[NIT], v2a[NIT];
    float s1 = 0.f, s2 = 0.f, m1 = 0.f, m2 = 0.f;
    #pragma unroll
    for (int it = 0; it < NIT; it++) {
        const float w = w_a[it], mk = msk[it];
        float v1 = mk * __fmaf_rn(w, b1v[it] - a1v[it], a1v[it]);
        float v2 = mk * __fmaf_rn(w, b2v[it] - a2v[it], a2v[it]);
        v1a[it] = v1;
        v2a[it] = v2;
        s1 += v1 * v1;
        s2 += v2 * v2;
        m1 = fmaxf(m1, fabsf(v1));
        m2 = fmaxf(m2, fabsf(v2));
    }

    // ---- block reductions: sq sums + maxabs ----
    #pragma unroll
    for (int o = 16; o > 0; o >>= 1) {
        s1 += __shfl_xor_sync(0xffffffffu, s1, o);
        s2 += __shfl_xor_sync(0xffffffffu, s2, o);
        m1 = fmaxf(m1, __shfl_xor_sync(0xffffffffu, m1, o));
        m2 = fmaxf(m2, __shfl_xor_sync(0xffffffffu, m2, o));
    }
    if ((tid & 31) == 0) {
        red1[tid >> 5] = s1;  red2[tid >> 5] = s2;
        redm1[tid >> 5] = m1; redm2[tid >> 5] = m2;
    }
    __syncthreads();
    if (tid == 0) {
        float t1 = 0.f, t2 = 0.f, q1 = 0.f, q2 = 0.f;
        #pragma unroll
        for (int w = 0; w < 8; w++) {
            t1 += red1[w]; t2 += red2[w];
            q1 = fmaxf(q1, redm1[w]); q2 = fmaxf(q2, redm2[w]);
        }
        g_sq1[b] = t1 * (1.0f / (float)M_C);
        g_sq2[b] = t2 * (1.0f / (float)M_C);
        g_scl1[b] = q1 * (1.0f / 127.0f);
        g_scl2[b] = q2 * (1.0f / 127.0f);
        s_inv1 = (q1 > 0.f) ? 127.0f / q1 : 0.f;
        s_inv2 = (q2 > 0.f) ? 127.0f / q2 : 0.f;
    }
    __syncthreads();

    // ---- phase D: quantize + store int8 ----
    const float i1 = s_inv1, i2 = s_inv2;
    #pragma unroll
    for (int it = 0; it < NIT; it++) {
        const int m = tid + it * 256;
        if (m < MP) {
            o1[m] = (int8_t)__float2int_rn(v1a[it] * i1);
            o2[m] = (int8_t)__float2int_rn(v2a[it] * i2);
        }
    }
}

// ---------------- kernel 3: int8 tensor-core GEMM + fused loss epilogue ---
// R11 pipeline, s8 IMMA m16n8k32 (2x FLOP/instr vs bf16 m16n8k16).
// 64x64 tiles, 8 warps (4x2), grid 256, stage = 64 k-bytes/row (nkb=47),
// 4-stage cp.async, register double-buffered fragments. The b16 ldmatrix
// addressing yields exactly the s8 k32 fragment layout (byte-verified).
#define GBM 64
#define GBN 64
#define GBKB 64                        // k-bytes (=elements) per stage
#define ROW_B 80                       // bytes per smem row (64 s8 + pad)
#define SA_STAGE (GBM * ROW_B)         // 5120 B
#define SB_STAGE (GBN * ROW_B)         // 5120 B
#define NSTAGE 4
#define SB_BASE (NSTAGE * SA_STAGE)    // 20480
#define SMEM_TOT (SB_BASE + NSTAGE * SB_STAGE)  // 40960 B

__device__ __forceinline__ void cp16(uint32_t dst, const void* src) {
    asm volatile("cp.async.cg.shared.global [%0], [%1], 16;\n"
                 :: "r"(dst), "l"(src));
}
__device__ __forceinline__ void ldsm_x4(uint32_t addr, uint32_t& r0, uint32_t& r1,
                                        uint32_t& r2, uint32_t& r3) {
    asm volatile("ldmatrix.sync.aligned.m8n8.x4.shared.b16 {%0,%1,%2,%3}, [%4];\n"
                 : "=r"(r0), "=r"(r1), "=r"(r2), "=r"(r3) : "r"(addr));
}
__device__ __forceinline__ void imma16832(int* c, const uint32_t* a, const uint32_t* b) {
    asm volatile(
        "mma.sync.aligned.m16n8k32.row.col.s32.s8.s8.s32 "
        "{%0,%1,%2,%3}, {%4,%5,%6,%7}, {%8,%9}, {%0,%1,%2,%3};\n"
        : "+r"(c[0]), "+r"(c[1]), "+r"(c[2]), "+r"(c[3])
        : "r"(a[0]), "r"(a[1]), "r"(a[2]), "r"(a[3]), "r"(b[0]), "r"(b[1]));
}

__global__ __launch_bounds__(256, 2) void gemm_loss_kernel(float* __restrict__ out, int B) {
    __shared__ __align__(16) unsigned char smem[SMEM_TOT];
    const uint32_t smem_u = (uint32_t)__cvta_generic_to_shared(smem);

    const int tid  = threadIdx.x;
    const int warp = tid >> 5;
    const int lane = tid & 31;

    const int8_t* Ag = g_q1 + (size_t)blockIdx.y * GBM * MP;
    const int8_t* Bg = g_q2 + (size_t)blockIdx.x * GBN * MP;

    const int a_row0 = tid >> 2, a_c = tid & 3;   // 64 rows x 4 16B-chunks

    const int nkb = MP / GBKB;    // 47

    auto load_stage = [&](int st, int kb) {
        const int k0 = kb * GBKB;
        cp16(smem_u + st * SA_STAGE + a_row0 * ROW_B + a_c * 16,
             Ag + (size_t)a_row0 * MP + k0 + a_c * 16);
        cp16(smem_u + SB_BASE + st * SB_STAGE + a_row0 * ROW_B + a_c * 16,
             Bg + (size_t)a_row0 * MP + k0 + a_c * 16);
    };

    load_stage(0, 0); asm volatile("cp.async.commit_group;\n" ::);
    load_stage(1, 1); asm volatile("cp.async.commit_group;\n" ::);
    load_stage(2, 2); asm volatile("cp.async.commit_group;\n" ::);

    const int wm = (warp >> 1) * 16;   // 4 warps along M
    const int wn = (warp & 1) * 32;    // 2 warps along N
    const int lr = lane & 7, q = lane >> 3;

    const uint32_t a_addr_base = smem_u + (wm + lr + (q & 1) * 8) * ROW_B + (q >> 1) * 16;
    const uint32_t b_addr_base = smem_u + SB_BASE + (wn + lr + (q >> 1) * 8) * ROW_B + (q & 1) * 16;

    // double-buffered fragments; each sub-step covers k32 (32 bytes)
    uint32_t af[2][4], bf[2][2][4];
    auto ldsm_step = [&](int st, int s, int pb) {
        const uint32_t aS = a_addr_base + st * SA_STAGE + s * 32;
        const uint32_t bS = b_addr_base + st * SB_STAGE + s * 32;
        ldsm_x4(aS, af[pb][0], af[pb][1], af[pb][2], af[pb][3]);
        ldsm_x4(bS,               bf[pb][0][0], bf[pb][0][1], bf[pb][0][2], bf[pb][0][3]);
        ldsm_x4(bS + 16 * ROW_B,  bf[pb][1][0], bf[pb][1][1], bf[pb][1][2], bf[pb][1][3]);
    };

    int acc[4][4];
    #pragma unroll
    for (int nf = 0; nf < 4; nf++)
        #pragma unroll
        for (int r = 0; r < 4; r++) acc[nf][r] = 0;

    auto mma_step = [&](int pb) {
        #pragma unroll
        for (int nf = 0; nf < 4; nf++) {
            uint32_t bb[2] = { bf[pb][nf >> 1][(nf & 1) * 2],
                               bf[pb][nf >> 1][(nf & 1) * 2 + 1] };
            imma16832(acc[nf], af[pb], bb);
        }
    };

    asm volatile("cp.async.wait_group 2;\n" ::);
    __syncthreads();
    ldsm_step(0, 0, 0);
    int pb = 0;

    for (int kb = 0; kb < nkb; kb++) {
        const int st = kb % NSTAGE;
        asm volatile("cp.async.wait_group 1;\n" ::);
        __syncthreads();
        if (kb + 3 < nkb) load_stage((kb + 3) % NSTAGE, kb + 3);
        asm volatile("cp.async.commit_group;\n" ::);

        ldsm_step(st, 1, pb ^ 1);
        mma_step(pb);
        pb ^= 1;

        if (kb + 1 < nkb) ldsm_step((kb + 1) % NSTAGE, 0, pb ^ 1);
        mma_step(pb);
        pb ^= 1;
    }

    // fused loss epilogue with dequant
    const float inv_m = 1.0f / (float)M_C;
    const int gm = blockIdx.y * GBM + wm;
    const int gn = blockIdx.x * GBN + wn;
    #pragma unroll
    for (int h = 0; h < 2; h++) {
        const int i = gm + (lane >> 2) + h * 8;
        const float s1 = g_sq1[i];
        const float base = s1 + g_sq2[i] + EPS_B;   // reference quirk: both i-indexed
        const float scale = 2.0f / base;
        const float dq_i = g_scl1[i] * inv_m;
        #pragma unroll
        for (int nf = 0; nf < 4; nf++) {
            const int j = gn + nf * 8 + (lane & 3) * 2;
            float dq0 = dq_i * g_scl2[j];
            float dq1 = dq_i * g_scl2[j + 1];
            float c0 = (float)acc[nf][h * 2 + 0] * dq0;
            float c1 = (float)acc[nf][h * 2 + 1] * dq1;
            float d0 = fmaxf(s1 + g_sq2[j]     - 2.0f * c0, 0.f);
            float d1 = fmaxf(s1 + g_sq2[j + 1] - 2.0f * c1, 0.f);
            float2 o = { sqrtf(d0 * scale), sqrtf(d1 * scale) };
            *(float2*)(out + (size_t)i * B + j) = o;
        }
    }
}

// ---------------- launch ----------------
extern "C" void kernel_launch(void* const* d_in, const int* in_sizes, int n_in,
                              void* d_out, int out_size) {
    const float* x  = (const float*)d_in[0];
    const float* y1 = (const float*)d_in[1];
    const float* y2 = (const float*)d_in[2];
    float* out = (float*)d_out;

    // out is [B, B] -> exact integer sqrt
    int B = 1;
    while ((long long)(B + 1) * (B + 1) <= (long long)out_size) B++;
    int N = in_sizes[0] / B;

    mm_init_kernel<<<1, 1>>>();
    minmax_kernel<<<16, 128>>>(x, B, N);
    interp_kernel<<<B, 256>>>(x, y1, y2, N);
    dim3 grid(B / GBN, B / GBM);   // (16, 16)
    gemm_loss_kernel<<<grid, 256>>>(out, B);
}